// round 13
// baseline (speedup 1.0000x reference)
#include <cuda_runtime.h>
#include <cuda_fp16.h>
#include <cstdint>

// Problem constants
#define N_NODES 100000
#define N_EDGES 400000
#define DIM     128
#define HID     768
#define TILE_M  128
#define N_TILES   (N_EDGES / TILE_M)       // 3125
#define G_TILES   ((N_NODES + 127) / 128)  // 782
#define N_STEPS 6                          // 768 / 128 n-cols

// fp16 frag tables (built by prep_w):
//  g_wprep: [step6][nt16][kt16][lane32][8B]  (K=256: [Wa/2 ; Wc])   = 393216 B
//  g_wmod : [step6][nt16][kt8 ][lane32][8B]  (K=128: Wb - 2*Wc)     = 196608 B
//  g_G    : per-node table, fp16 [100096][768]                      = 153.7 MB
__device__ __align__(16) __half g_wprep[HID * 256];
__device__ __align__(16) __half g_wmod[HID * 128];
__device__ __align__(16) __half g_G[100096 * HID];

static constexpr uint32_t BSTEP_G = 16 * 16 * 32 * 8;   // 65536
static constexpr uint32_t BSTEP_E = 16 * 8 * 32 * 8;    // 32768

// ---------------- edge-kernel SMEM ----------------
// A frags (t0*t1): [mt8][kt8][lane32][16B] = 32768
static constexpr int ESM_A    = 0;
static constexpr int ESM_B    = 32768;    // 2 x 32768
static constexpr int ESM_G    = 98304;    // 2 x 34816 (Gsum, 272B-padded rows)
static constexpr int ESM_W2   = 167936;   // 768 f32
static constexpr int ESM_B1   = 171008;   // 768 f32
static constexpr int ESM_PART = 174080;   // 4 x 128 f32
static constexpr int ESM_TOTAL = 176128;
static constexpr int GROW = 272;          // padded Gsum row stride

// ---------------- gprep SMEM ----------------
static constexpr int GSM_A = 0;           // [mt8][kt16][lane32][16B] = 65536
static constexpr int GSM_B = 65536;       // 2 x 65536
static constexpr int GSM_TOTAL = 196608;

// ---------------- helpers ----------------
__device__ __forceinline__ uint32_t smem_u32(const void* p) {
    uint32_t a;
    asm("{ .reg .u64 t; cvta.to.shared.u64 t, %1; cvt.u32.u64 %0, t; }" : "=r"(a) : "l"(p));
    return a;
}
__device__ __forceinline__ void cp16(uint32_t dst, const void* src) {
    asm volatile("cp.async.cg.shared.global [%0], [%1], 16;" :: "r"(dst), "l"(src) : "memory");
}
__device__ __forceinline__ void cp_commit() {
    asm volatile("cp.async.commit_group;" ::: "memory");
}
template <int N>
__device__ __forceinline__ void cp_wait() {
    asm volatile("cp.async.wait_group %0;" :: "n"(N) : "memory");
}
__device__ __forceinline__ void mma16816(float* d, const uint32_t* a, const uint32_t* b) {
    asm volatile(
        "mma.sync.aligned.m16n8k16.row.col.f32.f16.f16.f32 "
        "{%0,%1,%2,%3}, {%4,%5,%6,%7}, {%8,%9}, {%0,%1,%2,%3};"
        : "+f"(d[0]), "+f"(d[1]), "+f"(d[2]), "+f"(d[3])
        : "r"(a[0]), "r"(a[1]), "r"(a[2]), "r"(a[3]), "r"(b[0]), "r"(b[1]));
}

// A-fragment smem byte offset, parameterized by ktiles-per-mtile
template <int KT>
__device__ __forceinline__ uint32_t a_frag_off(int r, int p) {
    int kt   = p >> 3;
    int kp   = p & 7;
    int ln   = ((r & 7) << 2) + (kp & 3);
    int word = ((r >> 3) & 1) + ((kp >> 2) << 1);
    int mt   = r >> 4;
    return (uint32_t)((((mt * KT + kt) << 9) + (ln << 4) + (word << 2)));
}

// ---------------- prep: build fp16 frag tables ----------------
__global__ void prep_w_kernel(const float* __restrict__ W1) {
    int i = blockIdx.x * blockDim.x + threadIdx.x;   // over 768*128
    if (i >= HID * 128) return;
    int n = i >> 7;
    int k = i & 127;
    float wa = W1[n * 384 + k];
    float wb = W1[n * 384 + 128 + k];
    float wc = W1[n * 384 + 256 + k];

    int step = n >> 7;
    int np   = n & 127;
    int nt   = np >> 3;
    int g    = np & 7;
    int kt   = k >> 4;            // 0..7
    int kk   = k & 15;
    int w    = kk >> 3;
    int t    = (kk & 7) >> 1;
    int hb   = kk & 1;
    uint32_t fin = (uint32_t)(((g << 2) + t) << 3) + (uint32_t)(w << 2) + (uint32_t)(hb << 1);

    // wprep: kt slot kt for x-part (Wa/2), kt+8 for x^2-part (Wc)
    uint32_t oa = (uint32_t)step * BSTEP_G + (uint32_t)((nt * 16 + kt) << 8) + fin;
    uint32_t oc = (uint32_t)step * BSTEP_G + (uint32_t)((nt * 16 + 8 + kt) << 8) + fin;
    *(__half*)((char*)g_wprep + oa) = __float2half_rn(0.5f * wa);
    *(__half*)((char*)g_wprep + oc) = __float2half_rn(wc);
    // wmod = Wb - 2*Wc
    uint32_t om = (uint32_t)step * BSTEP_E + (uint32_t)((nt * 8 + kt) << 8) + fin;
    *(__half*)((char*)g_wmod + om) = __float2half_rn(wb - 2.f * wc);
}

// ---------------- gprep: G[v] = (Wa/2) x + Wc x^2  (fp16 out) ----------------
__global__ void __launch_bounds__(256) gprep_kernel(const float* __restrict__ x) {
    extern __shared__ char smem[];
    const uint32_t sb = smem_u32(smem);
    const int tid  = threadIdx.x;
    const int lane = tid & 31;
    const int wid  = tid >> 5;
    const int mg   = wid & 1;
    const int ng   = wid >> 1;
    const int nb   = blockIdx.x * 128;

    // prologue: B steps 0,1
    {
        const char* g0 = (const char*)g_wprep + (uint32_t)tid * 16u;
#pragma unroll
        for (int j = 0; j < 16; j++)
            cp16(sb + GSM_B + tid * 16 + j * 4096, g0 + j * 4096);
        cp_commit();
        const char* g1 = (const char*)g_wprep + BSTEP_G + (uint32_t)tid * 16u;
#pragma unroll
        for (int j = 0; j < 16; j++)
            cp16(sb + GSM_B + BSTEP_G + tid * 16 + j * 4096, g1 + j * 4096);
        cp_commit();
    }

    // A build: [x | x^2], K=256 -> 16 kt. 2 threads/row, 16 float4 each (full half-row).
    {
        const int r  = tid >> 1;
        const int hf = tid & 1;
        int v = nb + r;
        if (v >= N_NODES) v = 0;
        const float4* px = (const float4*)(x + (size_t)v * DIM + hf * 64);
        char* As = smem + GSM_A;
#pragma unroll
        for (int q = 0; q < 16; q++) {
            float4 a = px[q];
            int p = hf * 32 + 2 * q;
            __half2 h;
            h = __floats2half2_rn(a.x, a.y);
            *(uint32_t*)(As + a_frag_off<16>(r, p))          = *(uint32_t*)&h;
            h = __floats2half2_rn(a.z, a.w);
            *(uint32_t*)(As + a_frag_off<16>(r, p + 1))      = *(uint32_t*)&h;
            h = __floats2half2_rn(a.x * a.x, a.y * a.y);
            *(uint32_t*)(As + a_frag_off<16>(r, 64 + p))     = *(uint32_t*)&h;
            h = __floats2half2_rn(a.z * a.z, a.w * a.w);
            *(uint32_t*)(As + a_frag_off<16>(r, 64 + p + 1)) = *(uint32_t*)&h;
        }
    }

    const int t4 = lane & 3;
    const int g  = lane >> 2;
    const uint32_t a_base = (uint32_t)GSM_A + (uint32_t)mg * 32768u + (uint32_t)lane * 16u;
    const uint32_t b_rel  = (uint32_t)ng * 16384u + (uint32_t)lane * 8u;   // ntile = ng*4

#pragma unroll 1
    for (int s = 0; s < N_STEPS; s++) {
        cp_wait<1>();
        __syncthreads();

        float C[16][4];
#pragma unroll
        for (int f = 0; f < 16; f++)
#pragma unroll
            for (int v2 = 0; v2 < 4; v2++) C[f][v2] = 0.f;

        const uint32_t bbuf = (uint32_t)GSM_B + (uint32_t)(s & 1) * BSTEP_G + b_rel;
#pragma unroll
        for (int kt = 0; kt < 16; kt++) {
            uint4 A0 = *(const uint4*)(smem + a_base + (uint32_t)(0 * 16 + kt) * 512u);
            uint4 A1 = *(const uint4*)(smem + a_base + (uint32_t)(1 * 16 + kt) * 512u);
            uint4 A2 = *(const uint4*)(smem + a_base + (uint32_t)(2 * 16 + kt) * 512u);
            uint4 A3 = *(const uint4*)(smem + a_base + (uint32_t)(3 * 16 + kt) * 512u);
            // blocked ntiles: B_j at ntile ng*4 + j
            uint2 B0 = *(const uint2*)(smem + bbuf + (uint32_t)(0 * 16 + kt) * 256u);
            uint2 B1 = *(const uint2*)(smem + bbuf + (uint32_t)(1 * 16 + kt) * 256u + 4096u * 0u + 0u);
            uint2 B2 = *(const uint2*)(smem + bbuf + (uint32_t)(2 * 16 + kt) * 256u);
            uint2 B3 = *(const uint2*)(smem + bbuf + (uint32_t)(3 * 16 + kt) * 256u);
            mma16816(C[0],  (const uint32_t*)&A0, (const uint32_t*)&B0);
            mma16816(C[1],  (const uint32_t*)&A0, (const uint32_t*)&B1);
            mma16816(C[2],  (const uint32_t*)&A0, (const uint32_t*)&B2);
            mma16816(C[3],  (const uint32_t*)&A0, (const uint32_t*)&B3);
            mma16816(C[4],  (const uint32_t*)&A1, (const uint32_t*)&B0);
            mma16816(C[5],  (const uint32_t*)&A1, (const uint32_t*)&B1);
            mma16816(C[6],  (const uint32_t*)&A1, (const uint32_t*)&B2);
            mma16816(C[7],  (const uint32_t*)&A1, (const uint32_t*)&B3);
            mma16816(C[8],  (const uint32_t*)&A2, (const uint32_t*)&B0);
            mma16816(C[9],  (const uint32_t*)&A2, (const uint32_t*)&B1);
            mma16816(C[10], (const uint32_t*)&A2, (const uint32_t*)&B2);
            mma16816(C[11], (const uint32_t*)&A2, (const uint32_t*)&B3);
            mma16816(C[12], (const uint32_t*)&A3, (const uint32_t*)&B0);
            mma16816(C[13], (const uint32_t*)&A3, (const uint32_t*)&B1);
            mma16816(C[14], (const uint32_t*)&A3, (const uint32_t*)&B2);
            mma16816(C[15], (const uint32_t*)&A3, (const uint32_t*)&B3);
        }
        __syncthreads();
        if (s + 2 < N_STEPS) {
            const char* src = (const char*)g_wprep + (uint32_t)(s + 2) * BSTEP_G + (uint32_t)tid * 16u;
            uint32_t d = sb + GSM_B + (uint32_t)(s & 1) * BSTEP_G + tid * 16;
#pragma unroll
            for (int j = 0; j < 16; j++)
                cp16(d + j * 4096, src + j * 4096);
        }
        cp_commit();

        // write G fp16; B_bt at ntile (ng*4 + bt) -> col (ng*4+bt)*8 + t4*2
#pragma unroll
        for (int bt = 0; bt < 4; bt++) {
            const int c = s * 128 + (ng * 4 + bt) * 8 + t4 * 2;
#pragma unroll
            for (int mt = 0; mt < 4; mt++) {
                float* d = C[mt * 4 + bt];
                int R = nb + mg * 64 + mt * 16 + g;
                if (R < N_NODES) {
                    __half2 h0 = __floats2half2_rn(d[0], d[1]);
                    *(__half2*)(g_G + (size_t)R * HID + c) = h0;
                }
                if (R + 8 < N_NODES) {
                    __half2 h1 = __floats2half2_rn(d[2], d[3]);
                    *(__half2*)(g_G + (size_t)(R + 8) * HID + c) = h1;
                }
            }
        }
    }
}

// ---------------- edge kernel: D = (t0*t1) Wmod^T ; fold G + b1, relu, dot w2 ----------------
__global__ void __launch_bounds__(256) edge_kernel(
    const float* __restrict__ x,
    const int* __restrict__ ei,
    const float* __restrict__ b1g,
    const float* __restrict__ w2g,
    const float* __restrict__ b2g,
    float* __restrict__ out)
{
    extern __shared__ char smem[];
    const uint32_t sb = smem_u32(smem);
    const int tid  = threadIdx.x;
    const int lane = tid & 31;
    const int wid  = tid >> 5;
    const int mg   = wid & 1;
    const int ng   = wid >> 1;
    const int e0   = blockIdx.x * TILE_M;

    // prologue: B steps 0,1
    {
        const char* g0 = (const char*)g_wmod + (uint32_t)tid * 16u;
#pragma unroll
        for (int j = 0; j < 8; j++)
            cp16(sb + ESM_B + tid * 16 + j * 4096, g0 + j * 4096);
        cp_commit();
        const char* g1 = (const char*)g_wmod + BSTEP_E + (uint32_t)tid * 16u;
#pragma unroll
        for (int j = 0; j < 8; j++)
            cp16(sb + ESM_B + BSTEP_E + tid * 16 + j * 4096, g1 + j * 4096);
        cp_commit();
    }

    // stage w2 / b1
    float* w2s = (float*)(smem + ESM_W2);
    float* b1s = (float*)(smem + ESM_B1);
#pragma unroll
    for (int i = 0; i < 3; i++) { w2s[tid + i * 256] = w2g[tid + i * 256];
                                  b1s[tid + i * 256] = b1g[tid + i * 256]; }

    // per-thread edge assignment (2 threads per edge row)
    const int r  = tid >> 1;
    const int hf = tid & 1;
    const int i0 = ei[e0 + r];
    const int i1 = ei[N_EDGES + e0 + r];
    const __half* pg0 = g_G + (size_t)i0 * HID + hf * 64;
    const __half* pg1 = g_G + (size_t)i1 * HID + hf * 64;
    const uint32_t gsts = (uint32_t)ESM_G + (uint32_t)r * GROW + (uint32_t)hf * 128u;

    // A build: t0*t1, K=128 -> 8 kt. 2 threads/row, 16 float4 each (full half-row).
    {
        const float4* p0 = (const float4*)(x + (size_t)i0 * DIM + hf * 64);
        const float4* p1 = (const float4*)(x + (size_t)i1 * DIM + hf * 64);
        char* As = smem + ESM_A;
#pragma unroll
        for (int q = 0; q < 16; q++) {
            float4 a = p0[q];
            float4 c = p1[q];
            int p = hf * 32 + 2 * q;
            __half2 h;
            h = __floats2half2_rn(a.x * c.x, a.y * c.y);
            *(uint32_t*)(As + a_frag_off<8>(r, p))     = *(uint32_t*)&h;
            h = __floats2half2_rn(a.z * c.z, a.w * c.w);
            *(uint32_t*)(As + a_frag_off<8>(r, p + 1)) = *(uint32_t*)&h;
        }
    }

    // stage Gsum step 0 into buffer 0
    {
#pragma unroll
        for (int j = 0; j < 8; j++) {
            uint4 a = *(const uint4*)(pg0 + j * 8);
            uint4 b = *(const uint4*)(pg1 + j * 8);
            uint4 o;
            ((__half2*)&o)[0] = __hadd2(((const __half2*)&a)[0], ((const __half2*)&b)[0]);
            ((__half2*)&o)[1] = __hadd2(((const __half2*)&a)[1], ((const __half2*)&b)[1]);
            ((__half2*)&o)[2] = __hadd2(((const __half2*)&a)[2], ((const __half2*)&b)[2]);
            ((__half2*)&o)[3] = __hadd2(((const __half2*)&a)[3], ((const __half2*)&b)[3]);
            *(uint4*)(smem + gsts + j * 16) = o;
        }
    }

    float accv[8];
#pragma unroll
    for (int i = 0; i < 8; i++) accv[i] = 0.f;
    const int t4 = lane & 3;
    const int g  = lane >> 2;

    const uint32_t a_base = (uint32_t)ESM_A + (uint32_t)mg * 16384u + (uint32_t)lane * 16u;
    const uint32_t b_rel  = (uint32_t)ng * 8192u + (uint32_t)lane * 8u;   // ntile = ng*4

#pragma unroll 1
    for (int s = 0; s < N_STEPS; s++) {
        cp_wait<1>();
        __syncthreads();    // B(s) + Gsum(s) visible

        float C[16][4];
#pragma unroll
        for (int f = 0; f < 16; f++)
#pragma unroll
            for (int v2 = 0; v2 < 4; v2++) C[f][v2] = 0.f;

        const uint32_t bbuf = (uint32_t)ESM_B + (uint32_t)(s & 1) * BSTEP_E + b_rel;
#pragma unroll
        for (int kt = 0; kt < 8; kt++) {
            uint4 A0 = *(const uint4*)(smem + a_base + (uint32_t)(0 * 8 + kt) * 512u);
            uint4 A1 = *(const uint4*)(smem + a_base + (uint32_t)(1 * 8 + kt) * 512u);
            uint4 A2 = *(const uint4*)(smem + a_base + (uint32_t)(2 * 8 + kt) * 512u);
            uint4 A3 = *(const uint4*)(smem + a_base + (uint32_t)(3 * 8 + kt) * 512u);
            uint2 B0 = *(const uint2*)(smem + bbuf + (uint32_t)(0 * 8 + kt) * 256u);
            uint2 B1 = *(const uint2*)(smem + bbuf + (uint32_t)(1 * 8 + kt) * 256u);
            uint2 B2 = *(const uint2*)(smem + bbuf + (uint32_t)(2 * 8 + kt) * 256u);
            uint2 B3 = *(const uint2*)(smem + bbuf + (uint32_t)(3 * 8 + kt) * 256u);
            mma16816(C[0],  (const uint32_t*)&A0, (const uint32_t*)&B0);
            mma16816(C[1],  (const uint32_t*)&A0, (const uint32_t*)&B1);
            mma16816(C[2],  (const uint32_t*)&A0, (const uint32_t*)&B2);
            mma16816(C[3],  (const uint32_t*)&A0, (const uint32_t*)&B3);
            mma16816(C[4],  (const uint32_t*)&A1, (const uint32_t*)&B0);
            mma16816(C[5],  (const uint32_t*)&A1, (const uint32_t*)&B1);
            mma16816(C[6],  (const uint32_t*)&A1, (const uint32_t*)&B2);
            mma16816(C[7],  (const uint32_t*)&A1, (const uint32_t*)&B3);
            mma16816(C[8],  (const uint32_t*)&A2, (const uint32_t*)&B0);
            mma16816(C[9],  (const uint32_t*)&A2, (const uint32_t*)&B1);
            mma16816(C[10], (const uint32_t*)&A2, (const uint32_t*)&B2);
            mma16816(C[11], (const uint32_t*)&A2, (const uint32_t*)&B3);
            mma16816(C[12], (const uint32_t*)&A3, (const uint32_t*)&B0);
            mma16816(C[13], (const uint32_t*)&A3, (const uint32_t*)&B1);
            mma16816(C[14], (const uint32_t*)&A3, (const uint32_t*)&B2);
            mma16816(C[15], (const uint32_t*)&A3, (const uint32_t*)&B3);
        }
        __syncthreads();    // B(s) drained
        if (s + 2 < N_STEPS) {
            const char* src = (const char*)g_wmod + (uint32_t)(s + 2) * BSTEP_E + (uint32_t)tid * 16u;
            uint32_t d = sb + ESM_B + (uint32_t)(s & 1) * BSTEP_E + tid * 16;
#pragma unroll
            for (int j = 0; j < 8; j++)
                cp16(d + j * 4096, src + j * 4096);
        }
        cp_commit();

        // issue Gsum(s+1) loads (latency hidden under fold below)
        uint4 ga[8], gb[8];
        if (s + 1 < N_STEPS) {
            const __half* q0 = pg0 + (s + 1) * 128;
            const __half* q1 = pg1 + (s + 1) * 128;
#pragma unroll
            for (int j = 0; j < 8; j++) { ga[j] = *(const uint4*)(q0 + j * 8);
                                          gb[j] = *(const uint4*)(q1 + j * 8); }
        }

        // fold: relu(D + Gsum + b1) * w2
        const char* Gs = smem + ESM_G + (uint32_t)(s & 1) * 34816u;
#pragma unroll
        for (int bt = 0; bt < 4; bt++) {
            const int cl = (ng * 4 + bt) * 8 + t4 * 2;       // col within step
            const int c0 = s * 128 + cl;
            float2 bb = *(const float2*)&b1s[c0];
            float2 ww = *(const float2*)&w2s[c0];
#pragma unroll
            for (int mt = 0; mt < 4; mt++) {
                float* d = C[mt * 4 + bt];
                const int row = mg * 64 + mt * 16 + g;
                float2 g0 = __half22float2(*(const __half2*)(Gs + row * GROW + cl * 2));
                float2 g1 = __half22float2(*(const __half2*)(Gs + (row + 8) * GROW + cl * 2));
                accv[mt * 2 + 0] += fmaxf(d[0] + g0.x + bb.x, 0.f) * ww.x
                                 + fmaxf(d[1] + g0.y + bb.y, 0.f) * ww.y;
                accv[mt * 2 + 1] += fmaxf(d[2] + g1.x + bb.x, 0.f) * ww.x
                                 + fmaxf(d[3] + g1.y + bb.y, 0.f) * ww.y;
            }
        }

        // store Gsum(s+1) into the other buffer (reads of that buffer finished
        // in fold(s-1), before the sync at the top of this iteration)
        if (s + 1 < N_STEPS) {
            uint32_t dsts = gsts + (uint32_t)((s + 1) & 1) * 34816u;
#pragma unroll
            for (int j = 0; j < 8; j++) {
                uint4 o;
                ((__half2*)&o)[0] = __hadd2(((const __half2*)&ga[j])[0], ((const __half2*)&gb[j])[0]);
                ((__half2*)&o)[1] = __hadd2(((const __half2*)&ga[j])[1], ((const __half2*)&gb[j])[1]);
                ((__half2*)&o)[2] = __hadd2(((const __half2*)&ga[j])[2], ((const __half2*)&gb[j])[2]);
                ((__half2*)&o)[3] = __hadd2(((const __half2*)&ga[j])[3], ((const __half2*)&gb[j])[3]);
                *(uint4*)(smem + dsts + j * 16) = o;
            }
        }
    }

    // reduce 4 lanes sharing a g-group
#pragma unroll
    for (int i = 0; i < 8; i++) {
        accv[i] += __shfl_xor_sync(0xffffffffu, accv[i], 1);
        accv[i] += __shfl_xor_sync(0xffffffffu, accv[i], 2);
    }

    float* part = (float*)(smem + ESM_PART);
    __syncthreads();
    if (t4 == 0) {
#pragma unroll
        for (int mt = 0; mt < 4; mt++) {
            const int row = mg * 64 + mt * 16 + g;
            part[ng * 128 + row]     = accv[mt * 2 + 0];
            part[ng * 128 + row + 8] = accv[mt * 2 + 1];
        }
    }
    __syncthreads();
    if (tid < 128)
        out[e0 + tid] = part[tid] + part[128 + tid] + part[256 + tid] + part[384 + tid] + b2g[0];
}

// ---------------- launch ----------------
extern "C" void kernel_launch(void* const* d_in, const int* in_sizes, int n_in,
                              void* d_out, int out_size) {
    const float* x  = (const float*)d_in[0];
    const int*   ei = (const int*)d_in[1];   // int32 (JAX default: x64 disabled)
    const float* W1 = (const float*)d_in[5];
    const float* b1 = (const float*)d_in[6];
    const float* W2 = (const float*)d_in[7];
    const float* b2 = (const float*)d_in[8];
    float* out = (float*)d_out;

    prep_w_kernel<<<(HID * 128 + 255) / 256, 256>>>(W1);

    cudaFuncSetAttribute(gprep_kernel,
                         cudaFuncAttributeMaxDynamicSharedMemorySize, GSM_TOTAL);
    gprep_kernel<<<G_TILES, 256, GSM_TOTAL>>>(x);

    cudaFuncSetAttribute(edge_kernel,
                         cudaFuncAttributeMaxDynamicSharedMemorySize, ESM_TOTAL);
    edge_kernel<<<N_TILES, 256, ESM_TOTAL>>>(x, ei, b1, W2, b2, out);
}

// round 14
// speedup vs baseline: 1.3566x; 1.3566x over previous
#include <cuda_runtime.h>
#include <cuda_fp16.h>
#include <cstdint>

// Problem constants
#define N_NODES 100000
#define N_EDGES 400000
#define DIM     128
#define KDIM    384       // 3*DIM
#define HID     768       // 6*DIM
#define TILE_M  128
#define N_TILES (N_EDGES / TILE_M)   // 3125
#define KTILES  24
#define N_QTRS  24                   // 6 steps x 4 quarters

// W1 fp16, m16n8k16 B-fragment order, quarter-grouped:
// [step 6][qtr 4][ntile 16][kt6][lane 32][8B]  (24 KB per quarter)
__device__ __align__(16) __half g_w1frag[HID * KDIM];

static constexpr uint32_t B_STEP_BYTES = 16 * 24 * 32 * 8;   // 98304
static constexpr uint32_t B_QTR_BYTES  = B_STEP_BYTES / 4;   // 24576

// ---------------- SMEM layout ----------------
// A (feat frags): [mt8][kt24][lane32][16B] = 98304
static constexpr int SM_A    = 0;
static constexpr int SM_B    = 98304;    // 4 x 24576 ring
static constexpr int SM_W2   = 196608;   // 768 f32
static constexpr int SM_B1   = 199680;   // 768 f32
static constexpr int SM_PART = 202752;   // 4 x 128 f32
static constexpr int SM_MBAR = 204800;   // 4 full + 4 empty mbarriers (64 B)
static constexpr int SMEM_TOTAL = 204864;

// ---------------- helpers ----------------
__device__ __forceinline__ uint32_t smem_u32(const void* p) {
    uint32_t a;
    asm("{ .reg .u64 t; cvta.to.shared.u64 t, %1; cvt.u32.u64 %0, t; }" : "=r"(a) : "l"(p));
    return a;
}
__device__ __forceinline__ void cp16(uint32_t dst, const void* src) {
    asm volatile("cp.async.cg.shared.global [%0], [%1], 16;" :: "r"(dst), "l"(src) : "memory");
}
__device__ __forceinline__ void cp_arrive_noinc(uint32_t mbar) {
    asm volatile("cp.async.mbarrier.arrive.noinc.shared.b64 [%0];" :: "r"(mbar) : "memory");
}
__device__ __forceinline__ void mbar_init(uint32_t m, uint32_t cnt) {
    asm volatile("mbarrier.init.shared.b64 [%0], %1;" :: "r"(m), "r"(cnt) : "memory");
}
__device__ __forceinline__ void mbar_arrive(uint32_t m) {
    asm volatile("mbarrier.arrive.shared.b64 _, [%0];" :: "r"(m) : "memory");
}
__device__ __forceinline__ void mbar_wait(uint32_t m, uint32_t parity) {
    asm volatile(
        "{\n\t.reg .pred P;\n"
        "LAB%=:\n\t"
        "mbarrier.try_wait.parity.acquire.cta.shared::cta.b64 P, [%0], %1, 0x989680;\n\t"
        "@!P bra LAB%=;\n\t}"
        :: "r"(m), "r"(parity) : "memory");
}
__device__ __forceinline__ void mma16816(float* d, const uint32_t* a, const uint32_t* b) {
    asm volatile(
        "mma.sync.aligned.m16n8k16.row.col.f32.f16.f16.f32 "
        "{%0,%1,%2,%3}, {%4,%5,%6,%7}, {%8,%9}, {%0,%1,%2,%3};"
        : "+f"(d[0]), "+f"(d[1]), "+f"(d[2]), "+f"(d[3])
        : "r"(a[0]), "r"(a[1]), "r"(a[2]), "r"(a[3]), "r"(b[0]), "r"(b[1]));
}

// A-fragment smem byte offset for (row r in 0..127, kpair p in 0..191)
__device__ __forceinline__ uint32_t a_frag_off(int r, int p) {
    int kt   = p >> 3;
    int kp   = p & 7;
    int ln   = ((r & 7) << 2) + (kp & 3);
    int word = ((r >> 3) & 1) + ((kp >> 2) << 1);
    int mt   = r >> 4;
    return (uint32_t)(((mt * KTILES + kt) << 9) + (ln << 4) + (word << 2));
}

// ---------------- prep: W1 fp32 -> fp16 fragment-ordered (quarter-grouped) ----------------
__global__ void prep_w1_kernel(const float* __restrict__ W1) {
    int i = blockIdx.x * blockDim.x + threadIdx.x;
    if (i >= HID * KDIM) return;
    int n = i / KDIM;
    int k = i - n * KDIM;
    int step = n >> 7;            // 128 cols per step
    int np   = n & 127;
    int nt   = np >> 3;           // 16 ntiles per step
    int g    = np & 7;
    int kt   = k >> 4;            // 0..23
    int qtr  = kt / 6;
    int kt6  = kt - qtr * 6;
    int kk   = k & 15;
    int w    = kk >> 3;
    int t    = (kk & 7) >> 1;
    int hb   = kk & 1;
    uint32_t off = (uint32_t)step * B_STEP_BYTES + (uint32_t)qtr * B_QTR_BYTES
                 + (uint32_t)((nt * 6 + kt6) << 8)
                 + (uint32_t)(((g << 2) + t) << 3) + (uint32_t)(w << 2) + (uint32_t)(hb << 1);
    *(__half*)((char*)g_w1frag + off) = __float2half_rn(W1[i]);
}

// ---------------- main fused kernel (warp-specialized) ----------------
__global__ void __launch_bounds__(288) edge_mlp_ws(
    const float* __restrict__ x,
    const int* __restrict__ ei,     // int32 (JAX x64 disabled)
    const float* __restrict__ b1g,
    const float* __restrict__ w2g,
    const float* __restrict__ b2g,
    float* __restrict__ out)
{
    extern __shared__ char smem[];
    const uint32_t sb = smem_u32(smem);
    const int tid  = threadIdx.x;
    const int lane = tid & 31;
    const int wid  = tid >> 5;
    const bool producer = (wid == 8);
    const int e0 = blockIdx.x * TILE_M;

    const uint32_t FULL  = sb + SM_MBAR;       // 4 x 8 B
    const uint32_t EMPTY = sb + SM_MBAR + 32;  // 4 x 8 B

    if (tid == 0) {
#pragma unroll
        for (int i = 0; i < 4; i++) {
            mbar_init(FULL + i * 8, 32);    // 32 producer-thread cp-arrivals
            mbar_init(EMPTY + i * 8, 256);  // 256 consumer-thread arrivals
        }
    }
    __syncthreads();   // barriers initialized

    if (producer) {
        // pre-fill quarters 0..3 (ring initially empty; no waits)
#pragma unroll
        for (int q = 0; q < 4; q++) {
            const char* src = (const char*)g_w1frag + (uint32_t)q * B_QTR_BYTES + (uint32_t)lane * 16u;
            uint32_t dst = sb + SM_B + (uint32_t)q * B_QTR_BYTES + (uint32_t)lane * 16u;
#pragma unroll
            for (int j = 0; j < 48; j++)
                cp16(dst + j * 512, src + j * 512);
            cp_arrive_noinc(FULL + q * 8);
        }
    } else {
        // stage w2 / b1 (256 consumer threads)
        float* w2s = (float*)(smem + SM_W2);
        float* b1s = (float*)(smem + SM_B1);
#pragma unroll
        for (int i = 0; i < 3; i++) { w2s[tid + i * 256] = w2g[tid + i * 256];
                                      b1s[tid + i * 256] = b1g[tid + i * 256]; }

        // build feat tile into A-fragment smem (kpair bases: mean 0, prod 64, sqdiff 128)
        const int r  = tid & 127;
        const int qb = (tid >> 7) * 16;
        const int i0 = ei[e0 + r];
        const int i1 = ei[N_EDGES + e0 + r];
        const float4* p0 = (const float4*)x + (size_t)i0 * 32 + qb;
        const float4* p1 = (const float4*)x + (size_t)i1 * 32 + qb;
        char* As = smem + SM_A;
#pragma unroll 4
        for (int q = 0; q < 16; q++) {
            float4 a = p0[q];
            float4 c = p1[q];
            int qg = qb + q;
            __half2 h;
            h = __floats2half2_rn((a.x + c.x) * 0.5f, (a.y + c.y) * 0.5f);
            *(uint32_t*)(As + a_frag_off(r, 2 * qg))          = *(uint32_t*)&h;
            h = __floats2half2_rn((a.z + c.z) * 0.5f, (a.w + c.w) * 0.5f);
            *(uint32_t*)(As + a_frag_off(r, 2 * qg + 1))      = *(uint32_t*)&h;
            h = __floats2half2_rn(a.x * c.x, a.y * c.y);
            *(uint32_t*)(As + a_frag_off(r, 64 + 2 * qg))     = *(uint32_t*)&h;
            h = __floats2half2_rn(a.z * c.z, a.w * c.w);
            *(uint32_t*)(As + a_frag_off(r, 64 + 2 * qg + 1)) = *(uint32_t*)&h;
            float d0 = a.x - c.x, d1 = a.y - c.y, d2 = a.z - c.z, d3 = a.w - c.w;
            h = __floats2half2_rn(d0 * d0, d1 * d1);
            *(uint32_t*)(As + a_frag_off(r, 128 + 2 * qg))     = *(uint32_t*)&h;
            h = __floats2half2_rn(d2 * d2, d3 * d3);
            *(uint32_t*)(As + a_frag_off(r, 128 + 2 * qg + 1)) = *(uint32_t*)&h;
        }
    }
    __syncthreads();   // A + w2/b1 visible to all consumers

    if (producer) {
        // steady-state refills: quarter q into ring slot q&3 after drain of q-4
#pragma unroll 1
        for (int q = 4; q < N_QTRS; q++) {
            mbar_wait(EMPTY + (q & 3) * 8, ((q >> 2) - 1) & 1);
            const char* src = (const char*)g_w1frag + (uint32_t)q * B_QTR_BYTES + (uint32_t)lane * 16u;
            uint32_t dst = sb + SM_B + (uint32_t)(q & 3) * B_QTR_BYTES + (uint32_t)lane * 16u;
#pragma unroll
            for (int j = 0; j < 48; j++)
                cp16(dst + j * 512, src + j * 512);
            cp_arrive_noinc(FULL + (q & 3) * 8);
        }
    } else {
        const int mg = wid & 1;      // 2 m-groups (64 rows = 4 mtiles)
        const int ng = wid >> 1;     // 4 n-groups (32 cols per step)
        const int t4 = lane & 3;
        const int g  = lane >> 2;
        float* w2s = (float*)(smem + SM_W2);
        float* b1s = (float*)(smem + SM_B1);

        float accv[8];
#pragma unroll
        for (int i = 0; i < 8; i++) accv[i] = 0.f;

        const uint32_t a_base = (uint32_t)SM_A + (uint32_t)(mg * 4 * KTILES) * 512u + (uint32_t)lane * 16u;
        const uint32_t b_rel  = (uint32_t)ng * 6144u + (uint32_t)lane * 8u;   // ntile = ng*4

        float C[16][4];

#pragma unroll 1
        for (int q = 0; q < N_QTRS; q++) {
            const int qs = q & 3;
            mbar_wait(FULL + qs * 8, (q >> 2) & 1);

            if (qs == 0) {
#pragma unroll
                for (int f = 0; f < 16; f++)
#pragma unroll
                    for (int v = 0; v < 4; v++) C[f][v] = 0.f;
            }

            const uint32_t bbuf = (uint32_t)SM_B + (uint32_t)qs * B_QTR_BYTES + b_rel;
            const int ktb = qs * 6;
#pragma unroll
            for (int kt = 0; kt < 6; kt++) {
                uint4 A0 = *(const uint4*)(smem + a_base + (uint32_t)(0 * KTILES + ktb + kt) * 512u);
                uint4 A1 = *(const uint4*)(smem + a_base + (uint32_t)(1 * KTILES + ktb + kt) * 512u);
                uint4 A2 = *(const uint4*)(smem + a_base + (uint32_t)(2 * KTILES + ktb + kt) * 512u);
                uint4 A3 = *(const uint4*)(smem + a_base + (uint32_t)(3 * KTILES + ktb + kt) * 512u);
                uint2 B0 = *(const uint2*)(smem + bbuf + (uint32_t)(0 * 6 + kt) * 256u);
                uint2 B1 = *(const uint2*)(smem + bbuf + (uint32_t)(1 * 6 + kt) * 256u);
                uint2 B2 = *(const uint2*)(smem + bbuf + (uint32_t)(2 * 6 + kt) * 256u);
                uint2 B3 = *(const uint2*)(smem + bbuf + (uint32_t)(3 * 6 + kt) * 256u);
                mma16816(C[0],  (const uint32_t*)&A0, (const uint32_t*)&B0);
                mma16816(C[1],  (const uint32_t*)&A0, (const uint32_t*)&B1);
                mma16816(C[2],  (const uint32_t*)&A0, (const uint32_t*)&B2);
                mma16816(C[3],  (const uint32_t*)&A0, (const uint32_t*)&B3);
                mma16816(C[4],  (const uint32_t*)&A1, (const uint32_t*)&B0);
                mma16816(C[5],  (const uint32_t*)&A1, (const uint32_t*)&B1);
                mma16816(C[6],  (const uint32_t*)&A1, (const uint32_t*)&B2);
                mma16816(C[7],  (const uint32_t*)&A1, (const uint32_t*)&B3);
                mma16816(C[8],  (const uint32_t*)&A2, (const uint32_t*)&B0);
                mma16816(C[9],  (const uint32_t*)&A2, (const uint32_t*)&B1);
                mma16816(C[10], (const uint32_t*)&A2, (const uint32_t*)&B2);
                mma16816(C[11], (const uint32_t*)&A2, (const uint32_t*)&B3);
                mma16816(C[12], (const uint32_t*)&A3, (const uint32_t*)&B0);
                mma16816(C[13], (const uint32_t*)&A3, (const uint32_t*)&B1);
                mma16816(C[14], (const uint32_t*)&A3, (const uint32_t*)&B2);
                mma16816(C[15], (const uint32_t*)&A3, (const uint32_t*)&B3);
            }
            mbar_arrive(EMPTY + qs * 8);   // release: B reads done, slot reusable

            if (qs == 3) {
                const int s = q >> 2;
                const int nb = s * 128 + (ng * 4) * 8 + t4 * 2;
#pragma unroll
                for (int bt = 0; bt < 4; bt++) {
                    const int c0 = nb + bt * 8;
                    float2 bb = *(const float2*)&b1s[c0];
                    float2 ww = *(const float2*)&w2s[c0];
#pragma unroll
                    for (int mt = 0; mt < 4; mt++) {
                        float* d = C[mt * 4 + bt];
                        accv[mt * 2 + 0] += fmaxf(d[0] + bb.x, 0.f) * ww.x
                                         + fmaxf(d[1] + bb.y, 0.f) * ww.y;
                        accv[mt * 2 + 1] += fmaxf(d[2] + bb.x, 0.f) * ww.x
                                         + fmaxf(d[3] + bb.y, 0.f) * ww.y;
                    }
                }
            }
        }

        // reduce 4 lanes sharing a g-group
#pragma unroll
        for (int i = 0; i < 8; i++) {
            accv[i] += __shfl_xor_sync(0xffffffffu, accv[i], 1);
            accv[i] += __shfl_xor_sync(0xffffffffu, accv[i], 2);
        }

        float* part = (float*)(smem + SM_PART);
        if (t4 == 0) {
#pragma unroll
            for (int mt = 0; mt < 4; mt++) {
                const int row = mg * 64 + mt * 16 + g;
                part[ng * 128 + row]     = accv[mt * 2 + 0];
                part[ng * 128 + row + 8] = accv[mt * 2 + 1];
            }
        }
    }

    __syncthreads();   // all consumers done writing part; producer done
    float* part = (float*)(smem + SM_PART);
    if (tid < 128)
        out[e0 + tid] = part[tid] + part[128 + tid] + part[256 + tid] + part[384 + tid] + b2g[0];
}

// ---------------- launch ----------------
extern "C" void kernel_launch(void* const* d_in, const int* in_sizes, int n_in,
                              void* d_out, int out_size) {
    const float* x  = (const float*)d_in[0];
    const int*   ei = (const int*)d_in[1];   // int32 (JAX default: x64 disabled)
    // d_in[2] edge_attr3, d_in[3] edge_attr4, d_in[4] batch: unused by reference
    const float* W1 = (const float*)d_in[5];
    const float* b1 = (const float*)d_in[6];
    const float* W2 = (const float*)d_in[7];
    const float* b2 = (const float*)d_in[8];
    float* out = (float*)d_out;

    prep_w1_kernel<<<(HID * KDIM + 255) / 256, 256>>>(W1);

    cudaFuncSetAttribute(edge_mlp_ws,
                         cudaFuncAttributeMaxDynamicSharedMemorySize, SMEM_TOTAL);
    edge_mlp_ws<<<N_TILES, 288, SMEM_TOTAL>>>(x, ei, b1, W2, b2, out);
}

// round 15
// speedup vs baseline: 1.4023x; 1.0337x over previous
#include <cuda_runtime.h>
#include <cuda_fp16.h>
#include <cstdint>

// Problem constants
#define N_NODES 100000
#define N_EDGES 400000
#define DIM     128
#define KDIM    384       // 3*DIM
#define HID     768       // 6*DIM
#define TILE_M  128
#define N_TILES (N_EDGES / TILE_M)   // 3125
#define KTILES  24
#define N_STEPS 4                    // 768 / 192 n-cols per step
#define CPS     8                    // chunks per step (3 kt each)
#define N_CHUNKS 32                  // 4 steps x 8 chunks

// W1 fp16, m16n8k16 B-fragment order, chunk-grouped:
// [step 4][chunk 8][ntile 24][kt3][lane 32][8B]   (18 KB per chunk)
__device__ __align__(16) __half g_w1frag[HID * KDIM];

static constexpr uint32_t B_STEP_BYTES  = 24 * 24 * 32 * 8;   // 147456
static constexpr uint32_t B_CHUNK_BYTES = B_STEP_BYTES / 8;   // 18432

// ---------------- SMEM layout ----------------
// A (feat frags): [mt8][kt24][lane32][16B] = 98304
static constexpr int SM_A    = 0;
static constexpr int SM_B    = 98304;    // 4 x 18432 ring = 73728
static constexpr int SM_W2   = 172032;   // 768 f32
static constexpr int SM_B1   = 175104;   // 768 f32
static constexpr int SM_PART = 178176;   // 6 x 128 f32 = 3072
static constexpr int SM_MBAR = 181248;   // 4 full + 4 empty mbarriers
static constexpr int SMEM_TOTAL = 181312;

// ---------------- helpers ----------------
__device__ __forceinline__ uint32_t smem_u32(const void* p) {
    uint32_t a;
    asm("{ .reg .u64 t; cvta.to.shared.u64 t, %1; cvt.u32.u64 %0, t; }" : "=r"(a) : "l"(p));
    return a;
}
__device__ __forceinline__ void cp16(uint32_t dst, const void* src) {
    asm volatile("cp.async.cg.shared.global [%0], [%1], 16;" :: "r"(dst), "l"(src) : "memory");
}
__device__ __forceinline__ void cp_arrive_noinc(uint32_t mbar) {
    asm volatile("cp.async.mbarrier.arrive.noinc.shared.b64 [%0];" :: "r"(mbar) : "memory");
}
__device__ __forceinline__ void mbar_init(uint32_t m, uint32_t cnt) {
    asm volatile("mbarrier.init.shared.b64 [%0], %1;" :: "r"(m), "r"(cnt) : "memory");
}
__device__ __forceinline__ void mbar_arrive(uint32_t m) {
    asm volatile("mbarrier.arrive.shared.b64 _, [%0];" :: "r"(m) : "memory");
}
__device__ __forceinline__ void mbar_wait(uint32_t m, uint32_t parity) {
    asm volatile(
        "{\n\t.reg .pred P;\n"
        "LAB%=:\n\t"
        "mbarrier.try_wait.parity.acquire.cta.shared::cta.b64 P, [%0], %1, 0x989680;\n\t"
        "@!P bra LAB%=;\n\t}"
        :: "r"(m), "r"(parity) : "memory");
}
__device__ __forceinline__ void mma16816(float* d, const uint32_t* a, const uint32_t* b) {
    asm volatile(
        "mma.sync.aligned.m16n8k16.row.col.f32.f16.f16.f32 "
        "{%0,%1,%2,%3}, {%4,%5,%6,%7}, {%8,%9}, {%0,%1,%2,%3};"
        : "+f"(d[0]), "+f"(d[1]), "+f"(d[2]), "+f"(d[3])
        : "r"(a[0]), "r"(a[1]), "r"(a[2]), "r"(a[3]), "r"(b[0]), "r"(b[1]));
}

// A-fragment smem byte offset for (row r in 0..127, kpair p in 0..191)
__device__ __forceinline__ uint32_t a_frag_off(int r, int p) {
    int kt   = p >> 3;
    int kp   = p & 7;
    int ln   = ((r & 7) << 2) + (kp & 3);
    int word = ((r >> 3) & 1) + ((kp >> 2) << 1);
    int mt   = r >> 4;
    return (uint32_t)(((mt * KTILES + kt) << 9) + (ln << 4) + (word << 2));
}

// ---------------- prep: W1 fp32 -> fp16 fragment-ordered (chunk-grouped) ----------------
__global__ void prep_w1_kernel(const float* __restrict__ W1) {
    int i = blockIdx.x * blockDim.x + threadIdx.x;
    if (i >= HID * KDIM) return;
    int n = i / KDIM;
    int k = i - n * KDIM;
    int step = n / 192;           // 192 cols per step
    int np   = n - step * 192;
    int nt   = np >> 3;           // 24 ntiles per step
    int g    = np & 7;
    int kt   = k >> 4;            // 0..23
    int ch   = kt / 3;            // chunk within step (0..7)
    int kt3  = kt - ch * 3;
    int kk   = k & 15;
    int w    = kk >> 3;
    int t    = (kk & 7) >> 1;
    int hb   = kk & 1;
    uint32_t off = (uint32_t)step * B_STEP_BYTES + (uint32_t)ch * B_CHUNK_BYTES
                 + (uint32_t)((nt * 3 + kt3) << 8)
                 + (uint32_t)(((g << 2) + t) << 3) + (uint32_t)(w << 2) + (uint32_t)(hb << 1);
    *(__half*)((char*)g_w1frag + off) = __float2half_rn(W1[i]);
}

// ---------------- main fused kernel (warp-specialized, 12 consumers + 1 producer) ----------------
__global__ void __launch_bounds__(416, 1) edge_mlp_ws(
    const float* __restrict__ x,
    const int* __restrict__ ei,     // int32 (JAX x64 disabled)
    const float* __restrict__ b1g,
    const float* __restrict__ w2g,
    const float* __restrict__ b2g,
    float* __restrict__ out)
{
    extern __shared__ char smem[];
    const uint32_t sb = smem_u32(smem);
    const int tid  = threadIdx.x;
    const int lane = tid & 31;
    const int wid  = tid >> 5;
    const bool producer = (wid == 12);
    const int e0 = blockIdx.x * TILE_M;

    const uint32_t FULL  = sb + SM_MBAR;       // 4 x 8 B
    const uint32_t EMPTY = sb + SM_MBAR + 32;  // 4 x 8 B

    if (tid == 0) {
#pragma unroll
        for (int i = 0; i < 4; i++) {
            mbar_init(FULL + i * 8, 32);    // producer cp-arrivals (32 lanes, noinc)
            mbar_init(EMPTY + i * 8, 384);  // 12 consumer warps x 32 threads
        }
    }
    __syncthreads();   // barriers initialized

    if (producer) {
        // pre-fill chunks 0..3 (ring initially empty)
#pragma unroll
        for (int q = 0; q < 4; q++) {
            const char* src = (const char*)g_w1frag + (uint32_t)q * B_CHUNK_BYTES + (uint32_t)lane * 16u;
            uint32_t dst = sb + SM_B + (uint32_t)q * B_CHUNK_BYTES + (uint32_t)lane * 16u;
#pragma unroll
            for (int j = 0; j < 36; j++)
                cp16(dst + j * 512, src + j * 512);
            cp_arrive_noinc(FULL + q * 8);
        }
    } else if (tid < 256) {
        // stage w2 / b1
        float* w2s = (float*)(smem + SM_W2);
        float* b1s = (float*)(smem + SM_B1);
#pragma unroll
        for (int i = 0; i < 3; i++) { w2s[tid + i * 256] = w2g[tid + i * 256];
                                      b1s[tid + i * 256] = b1g[tid + i * 256]; }

        // build feat tile (kpair bases: mean 0, prod 64, sqdiff 128); 2 threads/row
        const int r  = tid & 127;
        const int qb = (tid >> 7) * 16;
        const int i0 = ei[e0 + r];
        const int i1 = ei[N_EDGES + e0 + r];
        const float4* p0 = (const float4*)x + (size_t)i0 * 32 + qb;
        const float4* p1 = (const float4*)x + (size_t)i1 * 32 + qb;
        char* As = smem + SM_A;
#pragma unroll 4
        for (int q = 0; q < 16; q++) {
            float4 a = p0[q];
            float4 c = p1[q];
            int qg = qb + q;
            __half2 h;
            h = __floats2half2_rn((a.x + c.x) * 0.5f, (a.y + c.y) * 0.5f);
            *(uint32_t*)(As + a_frag_off(r, 2 * qg))          = *(uint32_t*)&h;
            h = __floats2half2_rn((a.z + c.z) * 0.5f, (a.w + c.w) * 0.5f);
            *(uint32_t*)(As + a_frag_off(r, 2 * qg + 1))      = *(uint32_t*)&h;
            h = __floats2half2_rn(a.x * c.x, a.y * c.y);
            *(uint32_t*)(As + a_frag_off(r, 64 + 2 * qg))     = *(uint32_t*)&h;
            h = __floats2half2_rn(a.z * c.z, a.w * c.w);
            *(uint32_t*)(As + a_frag_off(r, 64 + 2 * qg + 1)) = *(uint32_t*)&h;
            float d0 = a.x - c.x, d1 = a.y - c.y, d2 = a.z - c.z, d3 = a.w - c.w;
            h = __floats2half2_rn(d0 * d0, d1 * d1);
            *(uint32_t*)(As + a_frag_off(r, 128 + 2 * qg))     = *(uint32_t*)&h;
            h = __floats2half2_rn(d2 * d2, d3 * d3);
            *(uint32_t*)(As + a_frag_off(r, 128 + 2 * qg + 1)) = *(uint32_t*)&h;
        }
    }
    __syncthreads();   // A + w2/b1 visible

    if (producer) {
        // steady-state: chunk q into ring slot q&3 after consumers drain q-4
#pragma unroll 1
        for (int q = 4; q < N_CHUNKS; q++) {
            mbar_wait(EMPTY + (q & 3) * 8, ((q >> 2) - 1) & 1);
            const char* src = (const char*)g_w1frag + (uint32_t)q * B_CHUNK_BYTES + (uint32_t)lane * 16u;
            uint32_t dst = sb + SM_B + (uint32_t)(q & 3) * B_CHUNK_BYTES + (uint32_t)lane * 16u;
#pragma unroll
            for (int j = 0; j < 36; j++)
                cp16(dst + j * 512, src + j * 512);
            cp_arrive_noinc(FULL + (q & 3) * 8);
        }
    } else {
        const int mg = wid & 1;      // 2 m-groups (64 rows = 4 mtiles each)
        const int ng = wid >> 1;     // 6 n-groups (32 cols per step each)
        const int t4 = lane & 3;
        const int g  = lane >> 2;
        float* w2s = (float*)(smem + SM_W2);
        float* b1s = (float*)(smem + SM_B1);

        float accv[8];
#pragma unroll
        for (int i = 0; i < 8; i++) accv[i] = 0.f;

        const uint32_t a_base = (uint32_t)SM_A + (uint32_t)(mg * 4 * KTILES) * 512u + (uint32_t)lane * 16u;
        const uint32_t b_rel  = (uint32_t)ng * 3072u + (uint32_t)lane * 8u;   // ntile = ng*4, nt stride 768

        float C[16][4];

#pragma unroll 1
        for (int q = 0; q < N_CHUNKS; q++) {
            const int slot = q & 3;
            const int cs   = q & 7;            // chunk within step
            mbar_wait(FULL + slot * 8, (q >> 2) & 1);

            if (cs == 0) {
#pragma unroll
                for (int f = 0; f < 16; f++)
#pragma unroll
                    for (int v = 0; v < 4; v++) C[f][v] = 0.f;
            }

            const uint32_t bbuf = (uint32_t)SM_B + (uint32_t)slot * B_CHUNK_BYTES + b_rel;
            const int ktb = cs * 3;            // kt base within K for A
#pragma unroll
            for (int kt = 0; kt < 3; kt++) {
                uint4 A0 = *(const uint4*)(smem + a_base + (uint32_t)(0 * KTILES + ktb + kt) * 512u);
                uint4 A1 = *(const uint4*)(smem + a_base + (uint32_t)(1 * KTILES + ktb + kt) * 512u);
                uint4 A2 = *(const uint4*)(smem + a_base + (uint32_t)(2 * KTILES + ktb + kt) * 512u);
                uint4 A3 = *(const uint4*)(smem + a_base + (uint32_t)(3 * KTILES + ktb + kt) * 512u);
                uint2 B0 = *(const uint2*)(smem + bbuf + (uint32_t)(0 * 3 + kt) * 256u);
                uint2 B1 = *(const uint2*)(smem + bbuf + (uint32_t)(1 * 3 + kt) * 256u);
                uint2 B2 = *(const uint2*)(smem + bbuf + (uint32_t)(2 * 3 + kt) * 256u);
                uint2 B3 = *(const uint2*)(smem + bbuf + (uint32_t)(3 * 3 + kt) * 256u);
                mma16816(C[0],  (const uint32_t*)&A0, (const uint32_t*)&B0);
                mma16816(C[1],  (const uint32_t*)&A0, (const uint32_t*)&B1);
                mma16816(C[2],  (const uint32_t*)&A0, (const uint32_t*)&B2);
                mma16816(C[3],  (const uint32_t*)&A0, (const uint32_t*)&B3);
                mma16816(C[4],  (const uint32_t*)&A1, (const uint32_t*)&B0);
                mma16816(C[5],  (const uint32_t*)&A1, (const uint32_t*)&B1);
                mma16816(C[6],  (const uint32_t*)&A1, (const uint32_t*)&B2);
                mma16816(C[7],  (const uint32_t*)&A1, (const uint32_t*)&B3);
                mma16816(C[8],  (const uint32_t*)&A2, (const uint32_t*)&B0);
                mma16816(C[9],  (const uint32_t*)&A2, (const uint32_t*)&B1);
                mma16816(C[10], (const uint32_t*)&A2, (const uint32_t*)&B2);
                mma16816(C[11], (const uint32_t*)&A2, (const uint32_t*)&B3);
                mma16816(C[12], (const uint32_t*)&A3, (const uint32_t*)&B0);
                mma16816(C[13], (const uint32_t*)&A3, (const uint32_t*)&B1);
                mma16816(C[14], (const uint32_t*)&A3, (const uint32_t*)&B2);
                mma16816(C[15], (const uint32_t*)&A3, (const uint32_t*)&B3);
            }
            mbar_arrive(EMPTY + slot * 8);   // slot drained

            if (cs == 7) {
                const int s = q >> 3;
                const int nb = s * 192 + (ng * 4) * 8 + t4 * 2;
#pragma unroll
                for (int bt = 0; bt < 4; bt++) {
                    const int c0 = nb + bt * 8;
                    float2 bb = *(const float2*)&b1s[c0];
                    float2 ww = *(const float2*)&w2s[c0];
#pragma unroll
                    for (int mt = 0; mt < 4; mt++) {
                        float* d = C[mt * 4 + bt];
                        accv[mt * 2 + 0] += fmaxf(d[0] + bb.x, 0.f) * ww.x
                                         + fmaxf(d[1] + bb.y, 0.f) * ww.y;
                        accv[mt * 2 + 1] += fmaxf(d[2] + bb.x, 0.f) * ww.x
                                         + fmaxf(d[3] + bb.y, 0.f) * ww.y;
                    }
                }
            }
        }

        // reduce 4 lanes sharing a g-group
#pragma unroll
        for (int i = 0; i < 8; i++) {
            accv[i] += __shfl_xor_sync(0xffffffffu, accv[i], 1);
            accv[i] += __shfl_xor_sync(0xffffffffu, accv[i], 2);
        }

        float* part = (float*)(smem + SM_PART);
        if (t4 == 0) {
#pragma unroll
            for (int mt = 0; mt < 4; mt++) {
                const int row = mg * 64 + mt * 16 + g;
                part[ng * 128 + row]     = accv[mt * 2 + 0];
                part[ng * 128 + row + 8] = accv[mt * 2 + 1];
            }
        }
    }

    __syncthreads();   // consumers wrote part; producer done
    float* part = (float*)(smem + SM_PART);
    if (tid < 128) {
        float v = part[tid] + part[128 + tid] + part[256 + tid]
                + part[384 + tid] + part[512 + tid] + part[640 + tid];
        out[e0 + tid] = v + b2g[0];
    }
}

// ---------------- launch ----------------
extern "C" void kernel_launch(void* const* d_in, const int* in_sizes, int n_in,
                              void* d_out, int out_size) {
    const float* x  = (const float*)d_in[0];
    const int*   ei = (const int*)d_in[1];   // int32 (JAX default: x64 disabled)
    // d_in[2] edge_attr3, d_in[3] edge_attr4, d_in[4] batch: unused by reference
    const float* W1 = (const float*)d_in[5];
    const float* b1 = (const float*)d_in[6];
    const float* W2 = (const float*)d_in[7];
    const float* b2 = (const float*)d_in[8];
    float* out = (float*)d_out;

    prep_w1_kernel<<<(HID * KDIM + 255) / 256, 256>>>(W1);

    cudaFuncSetAttribute(edge_mlp_ws,
                         cudaFuncAttributeMaxDynamicSharedMemorySize, SMEM_TOTAL);
    edge_mlp_ws<<<N_TILES, 416, SMEM_TOTAL>>>(x, ei, b1, W2, b2, out);
}